// round 15
// baseline (speedup 1.0000x reference)
#include <cuda_runtime.h>

// Grad3D: out = |dx| + |dy| + |dz| with central differences, zero-padded.
// x shape (4, 1, 192, 224, 192) fp32, contiguous.
// R6 smem structure, 2 quads per thread: thread (r,q) owns float4 quads q and
// q+24 of its row (32B apart by 96 floats). Doubles DRAM MLP per thread,
// halves barrier participants (240 thr), 5 blocks/SM.

#define Nn 4
#define Dd 192
#define Hh 224
#define Ww 192
#define HW (Hh * Ww)          // 43008
#define DHW (Dd * HW)         // 8257536

#define BH 8                  // H output rows per block
#define DCHUNK 16             // D planes per block
#define NROWS (BH + 2)        // incl. halo rows (10)
#define ROWSTRIDE 200         // floats/row (800B): [3]=zero(w=-1), [4..195]=data, [196]=zero(w=192)
#define QT 24                 // threads per row (each owns 2 of the 48 quads)
#define THREADS (NROWS * QT)  // 240
#define BOFF 96               // float offset between a thread's two quads

__global__ void __launch_bounds__(THREADS, 5)
grad3d_kernel(const float* __restrict__ x, float* __restrict__ out)
{
    __shared__ __align__(16) float sm[2][NROWS * ROWSTRIDE];

    const int tid  = threadIdx.x;
    const int r    = tid / QT;            // 0..9 (r=0, r=9 are halo rows)
    const int q    = tid - r * QT;        // 0..23
    const int h0   = blockIdx.x * BH;     // 0..216
    const int d0   = blockIdx.y * DCHUNK; // 0..176
    const int dend = d0 + DCHUNK;
    const int n    = blockIdx.z;
    const int gh   = h0 - 1 + r;
    const bool inH  = (gh >= 0) && (gh < Hh);
    const bool comp = (r >= 1) && (r <= BH);

    // Zero guard columns (w=-1 at [3], w=W at [196]) in both buffers.
    if (q == 0) {
        sm[0][r * ROWSTRIDE + 3] = 0.0f;
        sm[0][r * ROWSTRIDE + 4 + Ww] = 0.0f;
        sm[1][r * ROWSTRIDE + 3] = 0.0f;
        sm[1][r * ROWSTRIDE + 4 + Ww] = 0.0f;
    }

    const float* __restrict__ src =
        x + (size_t)n * DHW + (size_t)(inH ? gh : 0) * Ww + q * 4;   // quad A; quad B at +BOFF
    float* __restrict__ dst =
        out + (size_t)n * DHW + (size_t)(comp ? gh : 0) * Ww + q * 4;

    const int soff = r * ROWSTRIDE + 4 + q * 4;   // quad A smem slot; B at +BOFF

    struct Q2 { float4 a, b; };
    auto ldq = [&](int d) -> Q2 {
        Q2 v;
        if (inH && (unsigned)d < (unsigned)Dd) {
            const float* s = src + (size_t)d * HW;
            v.a = *reinterpret_cast<const float4*>(s);
            v.b = *reinterpret_cast<const float4*>(s + BOFF);
        } else {
            v.a = make_float4(0.f, 0.f, 0.f, 0.f);
            v.b = v.a;
        }
        return v;
    };

    // Invariant entering iter d: regs pv=x[d-1], cu=x[d], nx=x[d+1]; sm[d&1]=plane d.
    Q2 pv = ldq(d0 - 1);
    Q2 cu = ldq(d0);
    Q2 nx = ldq(d0 + 1);
    *reinterpret_cast<float4*>(&sm[d0 & 1][soff])        = cu.a;
    *reinterpret_cast<float4*>(&sm[d0 & 1][soff + BOFF]) = cu.b;
    __syncthreads();

    for (int d = d0; d < dend; ++d) {
        // Prefetch plane d+2 (two independent LDGs; consumed next iteration).
        Q2 tmp;
        if (d + 2 <= dend) tmp = ldq(d + 2);
        else { tmp.a = make_float4(0.f, 0.f, 0.f, 0.f); tmp.b = tmp.a; }

        // Publish plane d+1 for next iteration's neighbor reads.
        if (d + 1 < dend) {
            *reinterpret_cast<float4*>(&sm[(d + 1) & 1][soff])        = nx.a;
            *reinterpret_cast<float4*>(&sm[(d + 1) & 1][soff + BOFF]) = nx.b;
        }

        if (comp) {
            const float* cb = &sm[d & 1][soff];
            float* drow = dst + (size_t)d * HW;

            // ---- quad A (w4 = q*4) ----
            {
                float  lf = cb[-1];                 // q==0 -> guard at [3]
                float  rt = cb[4];                  // interior smem (quad q+1)
                float4 up = *reinterpret_cast<const float4*>(cb - ROWSTRIDE);
                float4 dn = *reinterpret_cast<const float4*>(cb + ROWSTRIDE);
                float4 o;
                o.x = 0.5f * (fabsf(cu.a.y - lf)     + fabsf(dn.x - up.x) + fabsf(nx.a.x - pv.a.x));
                o.y = 0.5f * (fabsf(cu.a.z - cu.a.x) + fabsf(dn.y - up.y) + fabsf(nx.a.y - pv.a.y));
                o.z = 0.5f * (fabsf(cu.a.w - cu.a.y) + fabsf(dn.z - up.z) + fabsf(nx.a.z - pv.a.z));
                o.w = 0.5f * (fabsf(rt     - cu.a.z) + fabsf(dn.w - up.w) + fabsf(nx.a.w - pv.a.w));
                *reinterpret_cast<float4*>(drow) = o;
            }
            // ---- quad B (w4 = q*4 + 96) ----
            {
                const float* cbB = cb + BOFF;
                float  lf = cbB[-1];                // interior smem (quad q+23)
                float  rt = cbB[4];                 // q==23 -> guard at [196]
                float4 up = *reinterpret_cast<const float4*>(cbB - ROWSTRIDE);
                float4 dn = *reinterpret_cast<const float4*>(cbB + ROWSTRIDE);
                float4 o;
                o.x = 0.5f * (fabsf(cu.b.y - lf)     + fabsf(dn.x - up.x) + fabsf(nx.b.x - pv.b.x));
                o.y = 0.5f * (fabsf(cu.b.z - cu.b.x) + fabsf(dn.y - up.y) + fabsf(nx.b.y - pv.b.y));
                o.z = 0.5f * (fabsf(cu.b.w - cu.b.y) + fabsf(dn.z - up.z) + fabsf(nx.b.z - pv.b.z));
                o.w = 0.5f * (fabsf(rt     - cu.b.z) + fabsf(dn.w - up.w) + fabsf(nx.b.w - pv.b.w));
                *reinterpret_cast<float4*>(drow + BOFF) = o;
            }
        }

        __syncthreads();   // sm[(d+1)&1] published; reads of sm[d&1] complete
        pv = cu; cu = nx; nx = tmp;
    }
}

extern "C" void kernel_launch(void* const* d_in, const int* in_sizes, int n_in,
                              void* d_out, int out_size)
{
    const float* x = (const float*)d_in[0];
    float* out = (float*)d_out;
    dim3 grid(Hh / BH, Dd / DCHUNK, Nn);   // 28 x 12 x 4 = 1344 blocks
    grad3d_kernel<<<grid, THREADS>>>(x, out);
}

// round 16
// speedup vs baseline: 1.1736x; 1.1736x over previous
#include <cuda_runtime.h>

// Grad3D: out = |dx| + |dy| + |dz| with central differences, zero-padded.
// x shape (4, 1, 192, 224, 192) fp32, contiguous.
// Register D-march (R6 structure) with prefetch distance 3: each thread owns
// one (h, w4) quad, marches DCHUNK planes. z-derivative & center in registers
// (4 live planes pv/cu/nx/n2 + 1 in flight); smem (2 plane buffers) serves
// lf/rt/up/dn. One barrier per plane. LDG(d+3) -> first use at iter d+2 gives
// ~2 barrier periods of latency slack.

#define Nn 4
#define Dd 192
#define Hh 224
#define Ww 192
#define HW (Hh * Ww)          // 43008
#define DHW (Dd * HW)         // 8257536

#define BH 8                  // H output rows per block
#define DCHUNK 16             // D planes per block
#define NROWS (BH + 2)        // incl. halo rows (10)
#define ROWSTRIDE 200         // floats/row (800B): [3]=zero(w=-1), [4..195]=data, [196]=zero(w=192)
#define QPERROW (Ww / 4)      // 48
#define THREADS (NROWS * QPERROW)  // 480

__global__ void __launch_bounds__(THREADS, 3)
grad3d_kernel(const float* __restrict__ x, float* __restrict__ out)
{
    __shared__ __align__(16) float sm[2][NROWS * ROWSTRIDE];

    const int tid  = threadIdx.x;
    const int r    = tid / QPERROW;       // 0..9 (r=0, r=9 are halo rows)
    const int q    = tid - r * QPERROW;   // 0..47
    const int h0   = blockIdx.x * BH;     // 0..216
    const int d0   = blockIdx.y * DCHUNK; // 0..176
    const int dend = d0 + DCHUNK;
    const int n    = blockIdx.z;
    const int gh   = h0 - 1 + r;
    const bool inH  = (gh >= 0) && (gh < Hh);
    const bool comp = (r >= 1) && (r <= BH);

    // Zero guard columns (w=-1 at [3], w=W at [196]) in both buffers.
    if (q == 0) {
        sm[0][r * ROWSTRIDE + 3] = 0.0f;
        sm[0][r * ROWSTRIDE + 4 + Ww] = 0.0f;
        sm[1][r * ROWSTRIDE + 3] = 0.0f;
        sm[1][r * ROWSTRIDE + 4 + Ww] = 0.0f;
    }

    const float* __restrict__ src =
        x + (size_t)n * DHW + (size_t)(inH ? gh : 0) * Ww + q * 4;
    float* __restrict__ dst =
        out + (size_t)n * DHW + (size_t)(comp ? gh : 0) * Ww + q * 4;

    const int soff = r * ROWSTRIDE + 4 + q * 4;

    auto ldq = [&](int d) -> float4 {
        if (inH && (unsigned)d < (unsigned)Dd)
            return *reinterpret_cast<const float4*>(src + (size_t)d * HW);
        return make_float4(0.f, 0.f, 0.f, 0.f);
    };

    // Invariant entering iter d: pv=x[d-1], cu=x[d], nx=x[d+1], n2=x[d+2];
    // sm[d&1] holds plane d.
    float4 pv = ldq(d0 - 1);
    float4 cu = ldq(d0);
    float4 nx = ldq(d0 + 1);
    float4 n2 = ldq(d0 + 2);
    *reinterpret_cast<float4*>(&sm[d0 & 1][soff]) = cu;
    __syncthreads();

    for (int d = d0; d < dend; ++d) {
        // Prefetch plane d+3 (becomes nx two rotations later; last useful load
        // is plane dend, issued at iter dend-3).
        float4 tmp = (d + 3 <= dend) ? ldq(d + 3)
                                     : make_float4(0.f, 0.f, 0.f, 0.f);

        // Publish plane d+1 for next iteration's neighbor reads.
        if (d + 1 < dend)
            *reinterpret_cast<float4*>(&sm[(d + 1) & 1][soff]) = nx;

        if (comp) {
            const float* cb = &sm[d & 1][soff];
            float  lf = cb[-1];                                          // guard at q==0
            float  rt = cb[4];                                           // guard at q==47
            float4 up = *reinterpret_cast<const float4*>(cb - ROWSTRIDE);
            float4 dn = *reinterpret_cast<const float4*>(cb + ROWSTRIDE);

            float4 o;
            o.x = 0.5f * (fabsf(cu.y - lf)   + fabsf(dn.x - up.x) + fabsf(nx.x - pv.x));
            o.y = 0.5f * (fabsf(cu.z - cu.x) + fabsf(dn.y - up.y) + fabsf(nx.y - pv.y));
            o.z = 0.5f * (fabsf(cu.w - cu.y) + fabsf(dn.z - up.z) + fabsf(nx.z - pv.z));
            o.w = 0.5f * (fabsf(rt   - cu.z) + fabsf(dn.w - up.w) + fabsf(nx.w - pv.w));

            *reinterpret_cast<float4*>(dst + (size_t)d * HW) = o;
        }

        __syncthreads();   // sm[(d+1)&1] published; reads of sm[d&1] complete
        pv = cu; cu = nx; nx = n2; n2 = tmp;
    }
}

extern "C" void kernel_launch(void* const* d_in, const int* in_sizes, int n_in,
                              void* d_out, int out_size)
{
    const float* x = (const float*)d_in[0];
    float* out = (float*)d_out;
    dim3 grid(Hh / BH, Dd / DCHUNK, Nn);   // 28 x 12 x 4 = 1344 blocks
    grad3d_kernel<<<grid, THREADS>>>(x, out);
}